// round 3
// baseline (speedup 1.0000x reference)
#include <cuda_runtime.h>
#include <math.h>

#define D 128
#define MAXN 50000
#define MAXE 600000

// ---------------- scratch (static device globals; no allocation) ----------------
__device__ float g_xu[MAXN * D];
__device__ float g_xi[MAXN * D];
__device__ float g_yu[MAXN * D];
__device__ float g_yi[MAXN * D];
__device__ float g_qW[MAXN * D];
__device__ float g_kk[MAXN * D];
__device__ float g_vv[MAXN * D];
__device__ float g_es[MAXE];
__device__ float g_Mt[D * D];
__device__ float g_cb[D];
__device__ float g_sum;
__device__ int   g_off_ui[MAXN + 1];
__device__ int   g_off_iu[MAXN + 1];
__device__ int   g_el_ui[MAXE];
__device__ int   g_el_iu[MAXE];
__device__ int   g_tmp[MAXN];

// ---------------- weight-space precompute: Mt[j,d] = sum_e qw[e,d]*W[e,j]; cb = qb @ W ----------------
__global__ void weight_prep(const float* __restrict__ qw, const float* __restrict__ qb,
                            const float* __restrict__ W,
                            float* __restrict__ Mt, float* __restrict__ cb)
{
    int id = blockIdx.x * blockDim.x + threadIdx.x;
    if (id < D * D) {
        int j = id / D, d = id % D;
        float s = 0.f;
        #pragma unroll 8
        for (int e = 0; e < D; ++e) s = fmaf(qw[e * D + d], W[e * D + j], s);
        Mt[j * D + d] = s;
    } else if (id < D * D + D) {
        int j = id - D * D;
        float s = 0.f;
        #pragma unroll 8
        for (int e = 0; e < D; ++e) s = fmaf(qb[e], W[e * D + j], s);
        cb[j] = s;
    }
}

// ---------------- GEMM: C[N,128] = X[N,128] @ A^T + bias, A stored [128 out][128 in] ----------------
__global__ __launch_bounds__(256) void gemm128(const float* __restrict__ X,
                                               const float* __restrict__ A,
                                               const float* __restrict__ bias,
                                               float* __restrict__ C, int N)
{
    __shared__ float Xs[32][68];
    __shared__ float As[32][68];
    const int tid  = threadIdx.x;
    const int tx   = tid & 15;   // n dir
    const int ty   = tid >> 4;   // m dir
    const int row0 = blockIdx.x * 64;
    const int col0 = blockIdx.y * 64;

    const int lm = tid >> 2;            // 0..63
    const int lk = (tid & 3) * 8;       // 0,8,16,24

    float acc[4][4] = {};

    for (int k0 = 0; k0 < D; k0 += 32) {
        // X tile (transposed into smem)
        int gr = row0 + lm;
        float4 a0, a1;
        if (gr < N) {
            const float* p = X + (size_t)gr * D + k0 + lk;
            a0 = *(const float4*)p;
            a1 = *(const float4*)(p + 4);
        } else {
            a0 = make_float4(0.f, 0.f, 0.f, 0.f);
            a1 = a0;
        }
        Xs[lk + 0][lm] = a0.x; Xs[lk + 1][lm] = a0.y; Xs[lk + 2][lm] = a0.z; Xs[lk + 3][lm] = a0.w;
        Xs[lk + 4][lm] = a1.x; Xs[lk + 5][lm] = a1.y; Xs[lk + 6][lm] = a1.z; Xs[lk + 7][lm] = a1.w;
        // A tile (always in-bounds: 128x128)
        const float* q = A + (size_t)(col0 + lm) * D + k0 + lk;
        float4 b0 = *(const float4*)q;
        float4 b1 = *(const float4*)(q + 4);
        As[lk + 0][lm] = b0.x; As[lk + 1][lm] = b0.y; As[lk + 2][lm] = b0.z; As[lk + 3][lm] = b0.w;
        As[lk + 4][lm] = b1.x; As[lk + 5][lm] = b1.y; As[lk + 6][lm] = b1.z; As[lk + 7][lm] = b1.w;
        __syncthreads();

        #pragma unroll
        for (int k = 0; k < 32; ++k) {
            const float4 av = *(const float4*)(&Xs[k][ty << 2]);
            const float4 bv = *(const float4*)(&As[k][tx << 2]);
            float ar[4] = {av.x, av.y, av.z, av.w};
            float br[4] = {bv.x, bv.y, bv.z, bv.w};
            #pragma unroll
            for (int i = 0; i < 4; ++i)
                #pragma unroll
                for (int j = 0; j < 4; ++j)
                    acc[i][j] = fmaf(ar[i], br[j], acc[i][j]);
        }
        __syncthreads();
    }

    const float4 bb = *(const float4*)(bias + col0 + (tx << 2));
    float bv[4] = {bb.x, bb.y, bb.z, bb.w};
    #pragma unroll
    for (int i = 0; i < 4; ++i) {
        int gr = row0 + (ty << 2) + i;
        if (gr < N) {
            float4 o;
            o.x = acc[i][0] + bv[0];
            o.y = acc[i][1] + bv[1];
            o.z = acc[i][2] + bv[2];
            o.w = acc[i][3] + bv[3];
            *(float4*)(C + (size_t)gr * D + col0 + (tx << 2)) = o;
        }
    }
}

// ---------------- CSR build ----------------
__global__ void count_kernel(const int* __restrict__ dst, int* __restrict__ deg, int E)
{
    for (int e = blockIdx.x * blockDim.x + threadIdx.x; e < E; e += gridDim.x * blockDim.x)
        atomicAdd(&deg[dst[e]], 1);
}

__global__ __launch_bounds__(1024) void scan_excl_kernel(const int* __restrict__ deg,
                                                         int* __restrict__ off, int n)
{
    __shared__ int sh[1024];
    int t = threadIdx.x;
    int c = (n + 1023) >> 10;
    int lo = t * c;
    int hi = lo + c; if (hi > n) hi = n;
    int s = 0;
    for (int i = lo; i < hi; ++i) s += deg[i];
    sh[t] = s;
    __syncthreads();
    for (int o = 1; o < 1024; o <<= 1) {
        int v = (t >= o) ? sh[t - o] : 0;
        __syncthreads();
        sh[t] += v;
        __syncthreads();
    }
    int base = sh[t] - s;
    for (int i = lo; i < hi; ++i) { off[i] = base; base += deg[i]; }
    if (t == 1023) off[n] = sh[1023];
}

__global__ void fill_kernel(const int* __restrict__ dst, int* __restrict__ cur,
                            int* __restrict__ elist, int E)
{
    for (int e = blockIdx.x * blockDim.x + threadIdx.x; e < E; e += gridDim.x * blockDim.x) {
        int p = atomicAdd(&cur[dst[e]], 1);
        elist[p] = e;
    }
}

// ---------------- edge score: es[e] = exp(lrelu(qW[src].k[dst]/sqrt(D))); sum -> gsum ----------------
__global__ __launch_bounds__(256) void edge_score(const float* __restrict__ q,
                                                  const float* __restrict__ kk,
                                                  const int* __restrict__ src,
                                                  const int* __restrict__ dst,
                                                  float* __restrict__ esc,
                                                  float* __restrict__ gsum, int E)
{
    const int lane = threadIdx.x & 31;
    const int warp = (blockIdx.x * 256 + threadIdx.x) >> 5;
    const int nw   = (gridDim.x * 256) >> 5;
    float lsum = 0.f;
    for (int e = warp; e < E; e += nw) {
        int s = src[e], d = dst[e];
        float4 a = *(const float4*)(q  + (size_t)s * D + (lane << 2));
        float4 b = *(const float4*)(kk + (size_t)d * D + (lane << 2));
        float p = a.x * b.x + a.y * b.y + a.z * b.z + a.w * b.w;
        #pragma unroll
        for (int o = 16; o; o >>= 1) p += __shfl_xor_sync(0xffffffffu, p, o);
        float sc = p * 0.08838834764831845f;   // 1/sqrt(128)
        sc = sc > 0.f ? sc : 0.01f * sc;       // leaky_relu
        float ex = expf(sc);
        if (lane == 0) { esc[e] = ex; lsum += ex; }
    }
    if (lane == 0) atomicAdd(gsum, lsum);
}

__global__ void zero1(float* p) { *p = 0.f; }

// ---------------- atomic-free gather aggregation: out[dst] += sum alpha * v[src] ----------------
__global__ __launch_bounds__(256) void gather_agg(const float* __restrict__ v,
                                                  const int* __restrict__ src,
                                                  const float* __restrict__ esc,
                                                  const float* __restrict__ gsum,
                                                  const int* __restrict__ off,
                                                  const int* __restrict__ elist,
                                                  float* __restrict__ out, int n)
{
    const int lane = threadIdx.x & 31;
    const int warp = (blockIdx.x * 256 + threadIdx.x) >> 5;
    const int nw   = (gridDim.x * 256) >> 5;
    const float inv = 1.0f / *gsum;
    for (int node = warp; node < n; node += nw) {
        int beg = off[node], end = off[node + 1];
        float4 a = make_float4(0.f, 0.f, 0.f, 0.f);
        for (int idx = beg; idx < end; ++idx) {
            int e = elist[idx];
            float al = esc[e] * inv;
            const float4 val = *(const float4*)(v + (size_t)src[e] * D + (lane << 2));
            a.x = fmaf(al, val.x, a.x);
            a.y = fmaf(al, val.y, a.y);
            a.z = fmaf(al, val.z, a.z);
            a.w = fmaf(al, val.w, a.w);
        }
        float* p = out + (size_t)node * D + (lane << 2);
        float4 c = *(const float4*)p;
        c.x += a.x; c.y += a.y; c.z += a.z; c.w += a.w;
        *(float4*)p = c;
    }
}

// ---------------- host-side orchestration ----------------
static void run_edge_type(const float* x_src, const float* x_dst, int Ns, int Nd,
                          const float* qw, const float* qb,
                          const float* kw, const float* kb,
                          const float* vw, const float* vb,
                          const float* W,
                          const int* src, const int* dst, int E,
                          const int* off, const int* elist,
                          float* out_dst,
                          float* pMt, float* pcb, float* pqW, float* pk, float* pv,
                          float* pes, float* psum)
{
    weight_prep<<<65, 256>>>(qw, qb, W, pMt, pcb);
    gemm128<<<dim3((Ns + 63) / 64, 2), 256>>>(x_src, pMt, pcb, pqW, Ns);
    gemm128<<<dim3((Nd + 63) / 64, 2), 256>>>(x_dst, kw, kb, pk, Nd);
    gemm128<<<dim3((Ns + 63) / 64, 2), 256>>>(x_src, vw, vb, pv, Ns);
    zero1<<<1, 1>>>(psum);
    edge_score<<<1480, 256>>>(pqW, pk, src, dst, pes, psum, E);
    gather_agg<<<740, 256>>>(pv, src, pes, psum, off, elist, out_dst, Nd);
}

extern "C" void kernel_launch(void* const* d_in, const int* in_sizes, int n_in,
                              void* d_out, int out_size)
{
    const float* x_user = (const float*)d_in[0];
    const float* x_item = (const float*)d_in[1];
    const int*   ei_ui  = (const int*)d_in[2];
    const int*   ei_iu  = (const int*)d_in[3];
    const float* q_w_user = (const float*)d_in[4];
    const float* q_b_user = (const float*)d_in[5];
    const float* k_w_user = (const float*)d_in[6];
    const float* k_b_user = (const float*)d_in[7];
    const float* v_w_user = (const float*)d_in[8];
    const float* v_b_user = (const float*)d_in[9];
    const float* q_w_item = (const float*)d_in[10];
    const float* q_b_item = (const float*)d_in[11];
    const float* k_w_item = (const float*)d_in[12];
    const float* k_b_item = (const float*)d_in[13];
    const float* v_w_item = (const float*)d_in[14];
    const float* v_b_item = (const float*)d_in[15];
    const float* W_ui = (const float*)d_in[16];
    const float* W_iu = (const float*)d_in[17];

    const int NU = in_sizes[0] / D;
    const int NI = in_sizes[1] / D;
    const int E_ui = in_sizes[2] / 2;
    const int E_iu = in_sizes[3] / 2;

    float *xu, *xi, *yu, *yi, *pqW, *pk, *pv, *pes, *pMt, *pcb, *psum;
    int *off_ui, *off_iu, *el_ui, *el_iu, *tmp;
    cudaGetSymbolAddress((void**)&xu, g_xu);
    cudaGetSymbolAddress((void**)&xi, g_xi);
    cudaGetSymbolAddress((void**)&yu, g_yu);
    cudaGetSymbolAddress((void**)&yi, g_yi);
    cudaGetSymbolAddress((void**)&pqW, g_qW);
    cudaGetSymbolAddress((void**)&pk, g_kk);
    cudaGetSymbolAddress((void**)&pv, g_vv);
    cudaGetSymbolAddress((void**)&pes, g_es);
    cudaGetSymbolAddress((void**)&pMt, g_Mt);
    cudaGetSymbolAddress((void**)&pcb, g_cb);
    cudaGetSymbolAddress((void**)&psum, g_sum);
    cudaGetSymbolAddress((void**)&off_ui, g_off_ui);
    cudaGetSymbolAddress((void**)&off_iu, g_off_iu);
    cudaGetSymbolAddress((void**)&el_ui, g_el_ui);
    cudaGetSymbolAddress((void**)&el_iu, g_el_iu);
    cudaGetSymbolAddress((void**)&tmp, g_tmp);

    const int* src_ui = ei_ui;
    const int* dst_ui = ei_ui + E_ui;
    const int* src_iu = ei_iu;
    const int* dst_iu = ei_iu + E_iu;

    // --- CSR by dst for each edge type (built once, used by both layers) ---
    cudaMemsetAsync(tmp, 0, (size_t)NI * sizeof(int));
    count_kernel<<<1024, 256>>>(dst_ui, tmp, E_ui);
    scan_excl_kernel<<<1, 1024>>>(tmp, off_ui, NI);
    cudaMemcpyAsync(tmp, off_ui, (size_t)NI * sizeof(int), cudaMemcpyDeviceToDevice);
    fill_kernel<<<1024, 256>>>(dst_ui, tmp, el_ui, E_ui);

    cudaMemsetAsync(tmp, 0, (size_t)NU * sizeof(int));
    count_kernel<<<1024, 256>>>(dst_iu, tmp, E_iu);
    scan_excl_kernel<<<1, 1024>>>(tmp, off_iu, NU);
    cudaMemcpyAsync(tmp, off_iu, (size_t)NU * sizeof(int), cudaMemcpyDeviceToDevice);
    fill_kernel<<<1024, 256>>>(dst_iu, tmp, el_iu, E_iu);

    // --- init current features ---
    cudaMemcpyAsync(xu, x_user, (size_t)NU * D * sizeof(float), cudaMemcpyDeviceToDevice);
    cudaMemcpyAsync(xi, x_item, (size_t)NI * D * sizeof(float), cudaMemcpyDeviceToDevice);

    float* out_f = (float*)d_out;

    for (int l = 0; l < 2; ++l) {
        const float* in_u = (l == 0) ? xu : yu;
        const float* in_i = (l == 0) ? xi : yi;
        float* out_u = (l == 0) ? yu : out_f;
        float* out_i = (l == 0) ? yi : (out_f + (size_t)NU * D);

        // accumulators start at x_dst (residual)
        cudaMemcpyAsync(out_u, in_u, (size_t)NU * D * sizeof(float), cudaMemcpyDeviceToDevice);
        cudaMemcpyAsync(out_i, in_i, (size_t)NI * D * sizeof(float), cudaMemcpyDeviceToDevice);

        const size_t wo = (size_t)l * D * D;
        const size_t bo = (size_t)l * D;

        // edge type user->item: q/v from user, k from item, bilinear W_ui, agg into items
        run_edge_type(in_u, in_i, NU, NI,
                      q_w_user + wo, q_b_user + bo,
                      k_w_item + wo, k_b_item + bo,
                      v_w_user + wo, v_b_user + bo,
                      W_ui + wo,
                      src_ui, dst_ui, E_ui, off_ui, el_ui,
                      out_i, pMt, pcb, pqW, pk, pv, pes, psum);

        // edge type item->user: q/v from item, k from user, bilinear W_iu, agg into users
        run_edge_type(in_i, in_u, NI, NU,
                      q_w_item + wo, q_b_item + bo,
                      k_w_user + wo, k_b_user + bo,
                      v_w_item + wo, v_b_item + bo,
                      W_iu + wo,
                      src_iu, dst_iu, E_iu, off_iu, el_iu,
                      out_u, pMt, pcb, pqW, pk, pv, pes, psum);
    }
}

// round 4
// speedup vs baseline: 1.8761x; 1.8761x over previous
#include <cuda_runtime.h>
#include <cuda_bf16.h>
#include <math.h>

#define D 128
#define MAXN 50000
#define MAXE 600000

// ---------------- scratch (static device globals; no allocation) ----------------
__device__ float          g_yu[MAXN * D];
__device__ float          g_yi[MAXN * D];
__device__ float          g_aggu[MAXN * D];
__device__ float          g_aggi[MAXN * D];
__device__ __nv_bfloat16  g_xbu[MAXN * D];
__device__ __nv_bfloat16  g_xbi[MAXN * D];
__device__ __nv_bfloat16  g_qW[MAXN * D];
__device__ __nv_bfloat16  g_kk[MAXN * D];
__device__ __nv_bfloat16  g_vv[MAXN * D];
__device__ __nv_bfloat16  g_Mtb[D * D];
__device__ __nv_bfloat16  g_Kb[D * D];
__device__ __nv_bfloat16  g_Vb[D * D];
__device__ float          g_cb[D];
__device__ float          g_sum[2];
__device__ int            g_off_ui[MAXN + 1];
__device__ int            g_off_iu[MAXN + 1];
__device__ int            g_src_ui[MAXE];
__device__ int            g_src_iu[MAXE];
__device__ int            g_tmp[MAXN];

// ---------------- per-pass weight prep: Mtb = bf16(qw^T @ ... folded), cb = qb@W; convert kw,vw ----
__global__ void prep_pass(const float* __restrict__ qw, const float* __restrict__ qb,
                          const float* __restrict__ W,
                          const float* __restrict__ kw, const float* __restrict__ vw,
                          __nv_bfloat16* __restrict__ Mtb, float* __restrict__ cb,
                          __nv_bfloat16* __restrict__ Kb, __nv_bfloat16* __restrict__ Vb,
                          float* __restrict__ psum)
{
    int sec = blockIdx.x / 65;
    int id  = (blockIdx.x % 65) * 256 + threadIdx.x;
    if (sec == 0) {
        if (blockIdx.x == 0 && threadIdx.x == 0) *psum = 0.f;
        if (id < D * D) {
            int j = id / D, d = id % D;
            float s = 0.f;
            #pragma unroll 8
            for (int e = 0; e < D; ++e) s = fmaf(qw[e * D + d], W[e * D + j], s);
            Mtb[j * D + d] = __float2bfloat16(s);
        } else if (id < D * D + D) {
            int j = id - D * D;
            float s = 0.f;
            #pragma unroll 8
            for (int e = 0; e < D; ++e) s = fmaf(qb[e], W[e * D + j], s);
            cb[j] = s;
        }
    } else if (sec == 1) {
        if (id < D * D) Kb[id] = __float2bfloat16(kw[id]);
    } else {
        if (id < D * D) Vb[id] = __float2bfloat16(vw[id]);
    }
}

// ---------------- fp32 -> bf16 convert (n multiple of 4) ----------------
__global__ void conv_b16(const float* __restrict__ x, __nv_bfloat16* __restrict__ y, int n4)
{
    int i = blockIdx.x * blockDim.x + threadIdx.x;
    if (i >= n4) return;
    float4 v = ((const float4*)x)[i];
    __nv_bfloat162 lo = __floats2bfloat162_rn(v.x, v.y);
    __nv_bfloat162 hi = __floats2bfloat162_rn(v.z, v.w);
    uint2 o;
    o.x = *(unsigned int*)&lo;
    o.y = *(unsigned int*)&hi;
    ((uint2*)y)[i] = o;
}

// ---------------- bf16 tensor-core GEMM: C[N,128] = bf16(X[N,128] @ Wm^T + bias) ----------------
__device__ __forceinline__ void mma16816(float c[4],
                                         unsigned a0, unsigned a1, unsigned a2, unsigned a3,
                                         unsigned b0, unsigned b1)
{
    asm volatile("mma.sync.aligned.m16n8k16.row.col.f32.bf16.bf16.f32 "
                 "{%0,%1,%2,%3}, {%4,%5,%6,%7}, {%8,%9}, {%0,%1,%2,%3};"
                 : "+f"(c[0]), "+f"(c[1]), "+f"(c[2]), "+f"(c[3])
                 : "r"(a0), "r"(a1), "r"(a2), "r"(a3), "r"(b0), "r"(b1));
}

#define GSTRIDE 136   // smem row stride in bf16 elems (272B = 68 words; 68 mod 32 = 4 -> conflict-free)

__global__ __launch_bounds__(256, 2) void gemm_b16(const __nv_bfloat16* __restrict__ X,
                                                   const __nv_bfloat16* __restrict__ Wm,
                                                   const float* __restrict__ bias,
                                                   __nv_bfloat16* __restrict__ C, int N)
{
    extern __shared__ __nv_bfloat16 sh[];
    __nv_bfloat16* Xs = sh;                   // [128][GSTRIDE]
    __nv_bfloat16* Ws = sh + 128 * GSTRIDE;   // [128][GSTRIDE]
    const int tid  = threadIdx.x;
    const int warp = tid >> 5, lane = tid & 31;
    const int row0 = blockIdx.x * 128;

    #pragma unroll
    for (int i = 0; i < 8; ++i) {
        int seg = tid + i * 256;
        int r = seg >> 4, c = (seg & 15) << 3;
        *(uint4*)(Ws + r * GSTRIDE + c) = *(const uint4*)(Wm + r * D + c);
    }
    #pragma unroll
    for (int i = 0; i < 8; ++i) {
        int seg = tid + i * 256;
        int r = seg >> 4, c = (seg & 15) << 3;
        int gr = row0 + r;
        uint4 val = make_uint4(0u, 0u, 0u, 0u);
        if (gr < N) val = *(const uint4*)(X + (size_t)gr * D + c);
        *(uint4*)(Xs + r * GSTRIDE + c) = val;
    }
    __syncthreads();

    const int wm = warp & 3;     // rows 32*wm .. +31 (two m16 tiles)
    const int wn = warp >> 2;    // cols 64*wn .. +63 (eight n8 tiles)
    const int qr = lane >> 2;    // 0..7
    const int kq = (lane & 3) * 2;

    float acc[2][8][4];
    #pragma unroll
    for (int m = 0; m < 2; ++m)
        #pragma unroll
        for (int nt = 0; nt < 8; ++nt)
            #pragma unroll
            for (int j = 0; j < 4; ++j) acc[m][nt][j] = 0.f;

    #pragma unroll
    for (int k0 = 0; k0 < D; k0 += 16) {
        unsigned a[2][4];
        #pragma unroll
        for (int m = 0; m < 2; ++m) {
            const __nv_bfloat16* base = Xs + (32 * wm + 16 * m + qr) * GSTRIDE + k0 + kq;
            a[m][0] = *(const unsigned*)(base);
            a[m][1] = *(const unsigned*)(base + 8 * GSTRIDE);
            a[m][2] = *(const unsigned*)(base + 8);
            a[m][3] = *(const unsigned*)(base + 8 * GSTRIDE + 8);
        }
        #pragma unroll
        for (int nt = 0; nt < 8; ++nt) {
            const __nv_bfloat16* bb = Ws + (64 * wn + nt * 8 + qr) * GSTRIDE + k0 + kq;
            unsigned b0 = *(const unsigned*)(bb);
            unsigned b1 = *(const unsigned*)(bb + 8);
            mma16816(acc[0][nt], a[0][0], a[0][1], a[0][2], a[0][3], b0, b1);
            mma16816(acc[1][nt], a[1][0], a[1][1], a[1][2], a[1][3], b0, b1);
        }
    }

    #pragma unroll
    for (int m = 0; m < 2; ++m) {
        int gr0 = row0 + 32 * wm + 16 * m + qr;
        int gr1 = gr0 + 8;
        #pragma unroll
        for (int nt = 0; nt < 8; ++nt) {
            int gc = 64 * wn + nt * 8 + kq;
            float b0f = bias[gc], b1f = bias[gc + 1];
            if (gr0 < N) {
                __nv_bfloat162 o = __floats2bfloat162_rn(acc[m][nt][0] + b0f, acc[m][nt][1] + b1f);
                *(__nv_bfloat162*)(C + (size_t)gr0 * D + gc) = o;
            }
            if (gr1 < N) {
                __nv_bfloat162 o = __floats2bfloat162_rn(acc[m][nt][2] + b0f, acc[m][nt][3] + b1f);
                *(__nv_bfloat162*)(C + (size_t)gr1 * D + gc) = o;
            }
        }
    }
}

// ---------------- CSR build ----------------
__global__ void count_kernel(const int* __restrict__ dst, int* __restrict__ deg, int E)
{
    for (int e = blockIdx.x * blockDim.x + threadIdx.x; e < E; e += gridDim.x * blockDim.x)
        atomicAdd(&deg[dst[e]], 1);
}

__global__ __launch_bounds__(1024) void scan_excl_kernel(const int* __restrict__ deg,
                                                         int* __restrict__ off, int n)
{
    __shared__ int sh[1024];
    int t = threadIdx.x;
    int c = (n + 1023) >> 10;
    int lo = t * c;
    int hi = lo + c; if (hi > n) hi = n;
    int s = 0;
    for (int i = lo; i < hi; ++i) s += deg[i];
    sh[t] = s;
    __syncthreads();
    for (int o = 1; o < 1024; o <<= 1) {
        int v = (t >= o) ? sh[t - o] : 0;
        __syncthreads();
        sh[t] += v;
        __syncthreads();
    }
    int base = sh[t] - s;
    for (int i = lo; i < hi; ++i) { off[i] = base; base += deg[i]; }
    if (t == 1023) off[n] = sh[1023];
}

__global__ void fill_kernel(const int* __restrict__ dst, const int* __restrict__ src,
                            int* __restrict__ cur, int* __restrict__ csrc, int E)
{
    for (int e = blockIdx.x * blockDim.x + threadIdx.x; e < E; e += gridDim.x * blockDim.x) {
        int p = atomicAdd(&cur[dst[e]], 1);
        csrc[p] = src[e];
    }
}

// ------------- fused edge: per dst node, agg = sum_e exp(lrelu(qW[src].k[dst]/sqrt(D))) * v[src] ----
__global__ __launch_bounds__(256) void fused_edge(const __nv_bfloat16* __restrict__ q,
                                                  const __nv_bfloat16* __restrict__ kk,
                                                  const __nv_bfloat16* __restrict__ v,
                                                  const int* __restrict__ off,
                                                  const int* __restrict__ csrc,
                                                  float* __restrict__ agg,
                                                  float* __restrict__ gsum, int n)
{
    const int lane = threadIdx.x & 31;
    const int warp = (blockIdx.x * 256 + threadIdx.x) >> 5;
    const int nw   = (gridDim.x * 256) >> 5;
    for (int node = warp; node < n; node += nw) {
        uint2 kr = *(const uint2*)(kk + (size_t)node * D + lane * 4);
        float2 kl = __bfloat1622float2(*(__nv_bfloat162*)&kr.x);
        float2 kh = __bfloat1622float2(*(__nv_bfloat162*)&kr.y);
        float a0 = 0.f, a1 = 0.f, a2 = 0.f, a3 = 0.f, S = 0.f;
        int beg = off[node], end = off[node + 1];
        for (int idx = beg; idx < end; ++idx) {
            int s = csrc[idx];
            uint2 qr = *(const uint2*)(q + (size_t)s * D + lane * 4);
            uint2 vr = *(const uint2*)(v + (size_t)s * D + lane * 4);
            float2 q0 = __bfloat1622float2(*(__nv_bfloat162*)&qr.x);
            float2 q1 = __bfloat1622float2(*(__nv_bfloat162*)&qr.y);
            float p = q0.x * kl.x + q0.y * kl.y + q1.x * kh.x + q1.y * kh.y;
            #pragma unroll
            for (int o = 16; o; o >>= 1) p += __shfl_xor_sync(0xffffffffu, p, o);
            float sc = p * 0.08838834764831845f;           // 1/sqrt(128)
            sc = sc > 0.f ? sc : 0.01f * sc;               // leaky_relu
            float ex = __expf(sc);
            float2 v0 = __bfloat1622float2(*(__nv_bfloat162*)&vr.x);
            float2 v1 = __bfloat1622float2(*(__nv_bfloat162*)&vr.y);
            a0 = fmaf(ex, v0.x, a0);
            a1 = fmaf(ex, v0.y, a1);
            a2 = fmaf(ex, v1.x, a2);
            a3 = fmaf(ex, v1.y, a3);
            S += ex;
        }
        float4 o = make_float4(a0, a1, a2, a3);
        *(float4*)(agg + (size_t)node * D + lane * 4) = o;
        if (lane == 0) atomicAdd(gsum, S);
    }
}

// ---------------- out = x + agg / S ; optionally also emit bf16 copy for next layer ----------------
__global__ void axpy_out(const float* __restrict__ xin, const float* __restrict__ agg,
                         const float* __restrict__ gsum, float* __restrict__ out,
                         __nv_bfloat16* __restrict__ outb, int n4)
{
    int i = blockIdx.x * blockDim.x + threadIdx.x;
    if (i >= n4) return;
    float inv = 1.0f / *gsum;
    float4 x = ((const float4*)xin)[i];
    float4 a = ((const float4*)agg)[i];
    float4 o;
    o.x = fmaf(inv, a.x, x.x);
    o.y = fmaf(inv, a.y, x.y);
    o.z = fmaf(inv, a.z, x.z);
    o.w = fmaf(inv, a.w, x.w);
    ((float4*)out)[i] = o;
    if (outb) {
        __nv_bfloat162 lo = __floats2bfloat162_rn(o.x, o.y);
        __nv_bfloat162 hi = __floats2bfloat162_rn(o.z, o.w);
        uint2 ob;
        ob.x = *(unsigned int*)&lo;
        ob.y = *(unsigned int*)&hi;
        ((uint2*)outb)[i] = ob;
    }
}

// ---------------- host-side orchestration ----------------
#define GEMM_SMEM (2 * 128 * GSTRIDE * (int)sizeof(__nv_bfloat16))

static void run_pass(const __nv_bfloat16* xb_src, const __nv_bfloat16* xb_dst, int Ns, int Nd,
                     const float* qw, const float* qb,
                     const float* kw, const float* kb,
                     const float* vw, const float* vb,
                     const float* W,
                     const int* off, const int* csrc,
                     float* agg, float* psum,
                     __nv_bfloat16* Mtb, float* cb, __nv_bfloat16* Kb, __nv_bfloat16* Vb,
                     __nv_bfloat16* qWb, __nv_bfloat16* kkb, __nv_bfloat16* vvb)
{
    prep_pass<<<195, 256>>>(qw, qb, W, kw, vw, Mtb, cb, Kb, Vb, psum);
    gemm_b16<<<(Ns + 127) / 128, 256, GEMM_SMEM>>>(xb_src, Mtb, cb, qWb, Ns);
    gemm_b16<<<(Nd + 127) / 128, 256, GEMM_SMEM>>>(xb_dst, Kb, kb, kkb, Nd);
    gemm_b16<<<(Ns + 127) / 128, 256, GEMM_SMEM>>>(xb_src, Vb, vb, vvb, Ns);
    fused_edge<<<1024, 256>>>(qWb, kkb, vvb, off, csrc, agg, psum, Nd);
}

extern "C" void kernel_launch(void* const* d_in, const int* in_sizes, int n_in,
                              void* d_out, int out_size)
{
    const float* x_user = (const float*)d_in[0];
    const float* x_item = (const float*)d_in[1];
    const int*   ei_ui  = (const int*)d_in[2];
    const int*   ei_iu  = (const int*)d_in[3];
    const float* q_w_user = (const float*)d_in[4];
    const float* q_b_user = (const float*)d_in[5];
    const float* k_w_user = (const float*)d_in[6];
    const float* k_b_user = (const float*)d_in[7];
    const float* v_w_user = (const float*)d_in[8];
    const float* v_b_user = (const float*)d_in[9];
    const float* q_w_item = (const float*)d_in[10];
    const float* q_b_item = (const float*)d_in[11];
    const float* k_w_item = (const float*)d_in[12];
    const float* k_b_item = (const float*)d_in[13];
    const float* v_w_item = (const float*)d_in[14];
    const float* v_b_item = (const float*)d_in[15];
    const float* W_ui = (const float*)d_in[16];
    const float* W_iu = (const float*)d_in[17];

    const int NU = in_sizes[0] / D;
    const int NI = in_sizes[1] / D;
    const int E_ui = in_sizes[2] / 2;
    const int E_iu = in_sizes[3] / 2;

    cudaFuncSetAttribute(gemm_b16, cudaFuncAttributeMaxDynamicSharedMemorySize, GEMM_SMEM);

    float *yu, *yi, *aggu, *aggi, *cb, *psum;
    __nv_bfloat16 *xbu, *xbi, *qWb, *kkb, *vvb, *Mtb, *Kb, *Vb;
    int *off_ui, *off_iu, *src_ui_c, *src_iu_c, *tmp;
    cudaGetSymbolAddress((void**)&yu, g_yu);
    cudaGetSymbolAddress((void**)&yi, g_yi);
    cudaGetSymbolAddress((void**)&aggu, g_aggu);
    cudaGetSymbolAddress((void**)&aggi, g_aggi);
    cudaGetSymbolAddress((void**)&xbu, g_xbu);
    cudaGetSymbolAddress((void**)&xbi, g_xbi);
    cudaGetSymbolAddress((void**)&qWb, g_qW);
    cudaGetSymbolAddress((void**)&kkb, g_kk);
    cudaGetSymbolAddress((void**)&vvb, g_vv);
    cudaGetSymbolAddress((void**)&Mtb, g_Mtb);
    cudaGetSymbolAddress((void**)&Kb, g_Kb);
    cudaGetSymbolAddress((void**)&Vb, g_Vb);
    cudaGetSymbolAddress((void**)&cb, g_cb);
    cudaGetSymbolAddress((void**)&psum, g_sum);
    cudaGetSymbolAddress((void**)&off_ui, g_off_ui);
    cudaGetSymbolAddress((void**)&off_iu, g_off_iu);
    cudaGetSymbolAddress((void**)&src_ui_c, g_src_ui);
    cudaGetSymbolAddress((void**)&src_iu_c, g_src_iu);
    cudaGetSymbolAddress((void**)&tmp, g_tmp);

    const int* src_ui = ei_ui;
    const int* dst_ui = ei_ui + E_ui;
    const int* src_iu = ei_iu;
    const int* dst_iu = ei_iu + E_iu;

    // --- CSR by dst for each edge type (stores src directly; built once, used by both layers) ---
    cudaMemsetAsync(tmp, 0, (size_t)NI * sizeof(int));
    count_kernel<<<1024, 256>>>(dst_ui, tmp, E_ui);
    scan_excl_kernel<<<1, 1024>>>(tmp, off_ui, NI);
    cudaMemcpyAsync(tmp, off_ui, (size_t)NI * sizeof(int), cudaMemcpyDeviceToDevice);
    fill_kernel<<<1024, 256>>>(dst_ui, src_ui, tmp, src_ui_c, E_ui);

    cudaMemsetAsync(tmp, 0, (size_t)NU * sizeof(int));
    count_kernel<<<1024, 256>>>(dst_iu, tmp, E_iu);
    scan_excl_kernel<<<1, 1024>>>(tmp, off_iu, NU);
    cudaMemcpyAsync(tmp, off_iu, (size_t)NU * sizeof(int), cudaMemcpyDeviceToDevice);
    fill_kernel<<<1024, 256>>>(dst_iu, src_iu, tmp, src_iu_c, E_iu);

    // --- bf16 copies of layer-0 inputs ---
    conv_b16<<<(NU * D / 4 + 255) / 256, 256>>>(x_user, xbu, NU * D / 4);
    conv_b16<<<(NI * D / 4 + 255) / 256, 256>>>(x_item, xbi, NI * D / 4);

    float* out_f = (float*)d_out;

    for (int l = 0; l < 2; ++l) {
        const float* in_u = (l == 0) ? x_user : yu;
        const float* in_i = (l == 0) ? x_item : yi;
        float* out_u = (l == 0) ? yu : out_f;
        float* out_i = (l == 0) ? yi : (out_f + (size_t)NU * D);

        const size_t wo = (size_t)l * D * D;
        const size_t bo = (size_t)l * D;

        // edge type user->item: q/v from user, k from item, bilinear W_ui, agg into items (sum slot 0)
        run_pass(xbu, xbi, NU, NI,
                 q_w_user + wo, q_b_user + bo,
                 k_w_item + wo, k_b_item + bo,
                 v_w_user + wo, v_b_user + bo,
                 W_ui + wo,
                 off_ui, src_ui_c, aggi, psum + 0,
                 Mtb, cb, Kb, Vb, qWb, kkb, vvb);

        // edge type item->user: q/v from item, k from user, bilinear W_iu, agg into users (sum slot 1)
        run_pass(xbi, xbu, NI, NU,
                 q_w_item + wo, q_b_item + bo,
                 k_w_user + wo, k_b_user + bo,
                 v_w_item + wo, v_b_item + bo,
                 W_iu + wo,
                 off_iu, src_iu_c, aggu, psum + 1,
                 Mtb, cb, Kb, Vb, qWb, kkb, vvb);

        // residual + normalized aggregation; layer 0 also emits bf16 inputs for layer 1
        axpy_out<<<(NU * D / 4 + 255) / 256, 256>>>(in_u, aggu, psum + 1, out_u,
                                                    (l == 0) ? xbu : (__nv_bfloat16*)nullptr,
                                                    NU * D / 4);
        axpy_out<<<(NI * D / 4 + 255) / 256, 256>>>(in_i, aggi, psum + 0, out_i,
                                                    (l == 0) ? xbi : (__nv_bfloat16*)nullptr,
                                                    NI * D / 4);
    }
}

// round 5
// speedup vs baseline: 2.0403x; 1.0875x over previous
#include <cuda_runtime.h>
#include <cuda_bf16.h>
#include <math.h>

#define D 128
#define MAXN 50000
#define MAXE 600000

// ---------------- scratch (static device globals; no allocation) ----------------
__device__ float          g_yu[MAXN * D];
__device__ float          g_yi[MAXN * D];
__device__ float          g_agg[2][MAXN * D];          // 0: items (ui pass), 1: users (iu pass)
__device__ __nv_bfloat16  g_xbu[MAXN * D];
__device__ __nv_bfloat16  g_xbi[MAXN * D];
__device__ __nv_bfloat16  g_q[2][MAXN * D];
__device__ __nv_bfloat16  g_k[2][MAXN * D];
__device__ __nv_bfloat16  g_v[2][MAXN * D];
__device__ __nv_bfloat16  g_Mtb[2][D * D];
__device__ __nv_bfloat16  g_Kb[2][D * D];
__device__ __nv_bfloat16  g_Vb[2][D * D];
__device__ float          g_cb[2][D];
__device__ float          g_sum[2];
__device__ int            g_off_ui[MAXN + 1];
__device__ int            g_off_iu[MAXN + 1];
__device__ int            g_src_ui[MAXE];
__device__ int            g_src_iu[MAXE];
__device__ int            g_tmp[MAXN];

// ---------------- batched per-layer weight prep (both edge-type passes) ----------------
struct PrepBatch {
    const float* qw[2]; const float* qb[2]; const float* W[2];
    const float* kw[2]; const float* vw[2];
    __nv_bfloat16* Mtb[2]; float* cb[2];
    __nv_bfloat16* Kb[2]; __nv_bfloat16* Vb[2];
    float* psum;
};

__global__ void prep_batch(PrepBatch pb)
{
    const int p  = blockIdx.y;
    const int bx = blockIdx.x;
    if (bx == 0 && threadIdx.x == 0) pb.psum[p] = 0.f;
    if (bx < 65) {
        int id = bx * 256 + threadIdx.x;
        if (id < D * D) {
            int j = id / D, d = id % D;
            const float* qw = pb.qw[p];
            const float* W  = pb.W[p];
            float s = 0.f;
            #pragma unroll 8
            for (int e = 0; e < D; ++e) s = fmaf(qw[e * D + d], W[e * D + j], s);
            pb.Mtb[p][j * D + d] = __float2bfloat16(s);
        } else if (id < D * D + D) {
            int j = id - D * D;
            const float* qb = pb.qb[p];
            const float* W  = pb.W[p];
            float s = 0.f;
            #pragma unroll 8
            for (int e = 0; e < D; ++e) s = fmaf(qb[e], W[e * D + j], s);
            pb.cb[p][j] = s;
        }
    } else if (bx < 129) {
        int id = (bx - 65) * 256 + threadIdx.x;
        pb.Kb[p][id] = __float2bfloat16(pb.kw[p][id]);
    } else {
        int id = (bx - 129) * 256 + threadIdx.x;
        pb.Vb[p][id] = __float2bfloat16(pb.vw[p][id]);
    }
}

// ---------------- fp32 -> bf16 convert (n multiple of 4) ----------------
__global__ void conv_b16(const float* __restrict__ x, __nv_bfloat16* __restrict__ y, int n4)
{
    int i = blockIdx.x * blockDim.x + threadIdx.x;
    if (i >= n4) return;
    float4 v = ((const float4*)x)[i];
    __nv_bfloat162 lo = __floats2bfloat162_rn(v.x, v.y);
    __nv_bfloat162 hi = __floats2bfloat162_rn(v.z, v.w);
    uint2 o;
    o.x = *(unsigned int*)&lo;
    o.y = *(unsigned int*)&hi;
    ((uint2*)y)[i] = o;
}

// ---------------- bf16 tensor-core batched GEMM: C[N,128] = bf16(X @ Wm^T + bias) ----------------
__device__ __forceinline__ void mma16816(float c[4],
                                         unsigned a0, unsigned a1, unsigned a2, unsigned a3,
                                         unsigned b0, unsigned b1)
{
    asm volatile("mma.sync.aligned.m16n8k16.row.col.f32.bf16.bf16.f32 "
                 "{%0,%1,%2,%3}, {%4,%5,%6,%7}, {%8,%9}, {%0,%1,%2,%3};"
                 : "+f"(c[0]), "+f"(c[1]), "+f"(c[2]), "+f"(c[3])
                 : "r"(a0), "r"(a1), "r"(a2), "r"(a3), "r"(b0), "r"(b1));
}

#define GSTRIDE 136   // smem row stride in bf16 elems; 68 words, 68 mod 32 = 4 -> conflict-free

struct GemmBatch {
    const __nv_bfloat16* X[6];
    const __nv_bfloat16* W[6];
    const float*         bias[6];
    __nv_bfloat16*       C[6];
    int                  N[6];
};

__global__ __launch_bounds__(256, 2) void gemm_batch(GemmBatch gb)
{
    extern __shared__ __nv_bfloat16 sh[];
    __nv_bfloat16* Xs = sh;                   // [128][GSTRIDE]
    __nv_bfloat16* Ws = sh + 128 * GSTRIDE;   // [128][GSTRIDE]
    const int g = blockIdx.y;
    const int N = gb.N[g];
    const int row0 = blockIdx.x * 128;
    if (row0 >= N) return;
    const __nv_bfloat16* __restrict__ X  = gb.X[g];
    const __nv_bfloat16* __restrict__ Wm = gb.W[g];
    const float* __restrict__ bias       = gb.bias[g];
    __nv_bfloat16* __restrict__ C        = gb.C[g];

    const int tid  = threadIdx.x;
    const int warp = tid >> 5, lane = tid & 31;

    #pragma unroll
    for (int i = 0; i < 8; ++i) {
        int seg = tid + i * 256;
        int r = seg >> 4, c = (seg & 15) << 3;
        *(uint4*)(Ws + r * GSTRIDE + c) = *(const uint4*)(Wm + r * D + c);
    }
    #pragma unroll
    for (int i = 0; i < 8; ++i) {
        int seg = tid + i * 256;
        int r = seg >> 4, c = (seg & 15) << 3;
        int gr = row0 + r;
        uint4 val = make_uint4(0u, 0u, 0u, 0u);
        if (gr < N) val = *(const uint4*)(X + (size_t)gr * D + c);
        *(uint4*)(Xs + r * GSTRIDE + c) = val;
    }
    __syncthreads();

    const int wm = warp & 3;
    const int wn = warp >> 2;
    const int qr = lane >> 2;
    const int kq = (lane & 3) * 2;

    float acc[2][8][4];
    #pragma unroll
    for (int m = 0; m < 2; ++m)
        #pragma unroll
        for (int nt = 0; nt < 8; ++nt)
            #pragma unroll
            for (int j = 0; j < 4; ++j) acc[m][nt][j] = 0.f;

    #pragma unroll
    for (int k0 = 0; k0 < D; k0 += 16) {
        unsigned a[2][4];
        #pragma unroll
        for (int m = 0; m < 2; ++m) {
            const __nv_bfloat16* base = Xs + (32 * wm + 16 * m + qr) * GSTRIDE + k0 + kq;
            a[m][0] = *(const unsigned*)(base);
            a[m][1] = *(const unsigned*)(base + 8 * GSTRIDE);
            a[m][2] = *(const unsigned*)(base + 8);
            a[m][3] = *(const unsigned*)(base + 8 * GSTRIDE + 8);
        }
        #pragma unroll
        for (int nt = 0; nt < 8; ++nt) {
            const __nv_bfloat16* bb = Ws + (64 * wn + nt * 8 + qr) * GSTRIDE + k0 + kq;
            unsigned b0 = *(const unsigned*)(bb);
            unsigned b1 = *(const unsigned*)(bb + 8);
            mma16816(acc[0][nt], a[0][0], a[0][1], a[0][2], a[0][3], b0, b1);
            mma16816(acc[1][nt], a[1][0], a[1][1], a[1][2], a[1][3], b0, b1);
        }
    }

    #pragma unroll
    for (int m = 0; m < 2; ++m) {
        int gr0 = row0 + 32 * wm + 16 * m + qr;
        int gr1 = gr0 + 8;
        #pragma unroll
        for (int nt = 0; nt < 8; ++nt) {
            int gc = 64 * wn + nt * 8 + kq;
            float b0f = bias[gc], b1f = bias[gc + 1];
            if (gr0 < N) {
                __nv_bfloat162 o = __floats2bfloat162_rn(acc[m][nt][0] + b0f, acc[m][nt][1] + b1f);
                *(__nv_bfloat162*)(C + (size_t)gr0 * D + gc) = o;
            }
            if (gr1 < N) {
                __nv_bfloat162 o = __floats2bfloat162_rn(acc[m][nt][2] + b0f, acc[m][nt][3] + b1f);
                *(__nv_bfloat162*)(C + (size_t)gr1 * D + gc) = o;
            }
        }
    }
}

// ---------------- CSR build ----------------
__global__ void count_kernel(const int* __restrict__ dst, int* __restrict__ deg, int E)
{
    for (int e = blockIdx.x * blockDim.x + threadIdx.x; e < E; e += gridDim.x * blockDim.x)
        atomicAdd(&deg[dst[e]], 1);
}

__global__ __launch_bounds__(1024) void scan_excl_kernel(const int* __restrict__ deg,
                                                         int* __restrict__ off, int n)
{
    __shared__ int sh[1024];
    int t = threadIdx.x;
    int c = (n + 1023) >> 10;
    int lo = t * c;
    int hi = lo + c; if (hi > n) hi = n;
    int s = 0;
    for (int i = lo; i < hi; ++i) s += deg[i];
    sh[t] = s;
    __syncthreads();
    for (int o = 1; o < 1024; o <<= 1) {
        int v = (t >= o) ? sh[t - o] : 0;
        __syncthreads();
        sh[t] += v;
        __syncthreads();
    }
    int base = sh[t] - s;
    for (int i = lo; i < hi; ++i) { off[i] = base; base += deg[i]; }
    if (t == 1023) off[n] = sh[1023];
}

__global__ void fill_kernel(const int* __restrict__ dst, const int* __restrict__ src,
                            int* __restrict__ cur, int* __restrict__ csrc, int E)
{
    for (int e = blockIdx.x * blockDim.x + threadIdx.x; e < E; e += gridDim.x * blockDim.x) {
        int p = atomicAdd(&cur[dst[e]], 1);
        csrc[p] = src[e];
    }
}

// ------------- batched fused edge pass (both edge types), edge loop unrolled x2 ----------------
struct EdgeBatch {
    const __nv_bfloat16* q[2];
    const __nv_bfloat16* k[2];
    const __nv_bfloat16* v[2];
    const int* off[2];
    const int* csrc[2];
    float* agg[2];
    float* psum;
    int n[2];
};

__device__ __forceinline__ float edot(uint2 qr, float2 kl, float2 kh)
{
    float2 q0 = __bfloat1622float2(*(__nv_bfloat162*)&qr.x);
    float2 q1 = __bfloat1622float2(*(__nv_bfloat162*)&qr.y);
    return q0.x * kl.x + q0.y * kl.y + q1.x * kh.x + q1.y * kh.y;
}

__global__ __launch_bounds__(256) void fused_edge_batch(EdgeBatch eb)
{
    const int p    = blockIdx.y;
    const int lane = threadIdx.x & 31;
    const int warp = (blockIdx.x * 256 + threadIdx.x) >> 5;
    const int nw   = (gridDim.x * 256) >> 5;
    const __nv_bfloat16* __restrict__ q  = eb.q[p];
    const __nv_bfloat16* __restrict__ kk = eb.k[p];
    const __nv_bfloat16* __restrict__ v  = eb.v[p];
    const int* __restrict__ off  = eb.off[p];
    const int* __restrict__ csrc = eb.csrc[p];
    float* __restrict__ agg      = eb.agg[p];
    const int n = eb.n[p];

    for (int node = warp; node < n; node += nw) {
        uint2 kr = *(const uint2*)(kk + (size_t)node * D + lane * 4);
        float2 kl = __bfloat1622float2(*(__nv_bfloat162*)&kr.x);
        float2 kh = __bfloat1622float2(*(__nv_bfloat162*)&kr.y);
        float a0 = 0.f, a1 = 0.f, a2 = 0.f, a3 = 0.f, S = 0.f;
        const int beg = off[node], end = off[node + 1];
        int idx = beg;
        for (; idx + 2 <= end; idx += 2) {
            int s0 = csrc[idx], s1 = csrc[idx + 1];
            uint2 q0r = *(const uint2*)(q + (size_t)s0 * D + lane * 4);
            uint2 q1r = *(const uint2*)(q + (size_t)s1 * D + lane * 4);
            uint2 v0r = *(const uint2*)(v + (size_t)s0 * D + lane * 4);
            uint2 v1r = *(const uint2*)(v + (size_t)s1 * D + lane * 4);
            float p0 = edot(q0r, kl, kh);
            float p1 = edot(q1r, kl, kh);
            #pragma unroll
            for (int o = 16; o; o >>= 1) {
                p0 += __shfl_xor_sync(0xffffffffu, p0, o);
                p1 += __shfl_xor_sync(0xffffffffu, p1, o);
            }
            float sc0 = p0 * 0.08838834764831845f;
            float sc1 = p1 * 0.08838834764831845f;
            sc0 = sc0 > 0.f ? sc0 : 0.01f * sc0;
            sc1 = sc1 > 0.f ? sc1 : 0.01f * sc1;
            float e0 = __expf(sc0);
            float e1 = __expf(sc1);
            float2 w0 = __bfloat1622float2(*(__nv_bfloat162*)&v0r.x);
            float2 w1 = __bfloat1622float2(*(__nv_bfloat162*)&v0r.y);
            float2 u0 = __bfloat1622float2(*(__nv_bfloat162*)&v1r.x);
            float2 u1 = __bfloat1622float2(*(__nv_bfloat162*)&v1r.y);
            a0 = fmaf(e0, w0.x, fmaf(e1, u0.x, a0));
            a1 = fmaf(e0, w0.y, fmaf(e1, u0.y, a1));
            a2 = fmaf(e0, w1.x, fmaf(e1, u1.x, a2));
            a3 = fmaf(e0, w1.y, fmaf(e1, u1.y, a3));
            S += e0 + e1;
        }
        if (idx < end) {
            int s0 = csrc[idx];
            uint2 q0r = *(const uint2*)(q + (size_t)s0 * D + lane * 4);
            uint2 v0r = *(const uint2*)(v + (size_t)s0 * D + lane * 4);
            float p0 = edot(q0r, kl, kh);
            #pragma unroll
            for (int o = 16; o; o >>= 1) p0 += __shfl_xor_sync(0xffffffffu, p0, o);
            float sc0 = p0 * 0.08838834764831845f;
            sc0 = sc0 > 0.f ? sc0 : 0.01f * sc0;
            float e0 = __expf(sc0);
            float2 w0 = __bfloat1622float2(*(__nv_bfloat162*)&v0r.x);
            float2 w1 = __bfloat1622float2(*(__nv_bfloat162*)&v0r.y);
            a0 = fmaf(e0, w0.x, a0);
            a1 = fmaf(e0, w0.y, a1);
            a2 = fmaf(e0, w1.x, a2);
            a3 = fmaf(e0, w1.y, a3);
            S += e0;
        }
        *(float4*)(agg + (size_t)node * D + lane * 4) = make_float4(a0, a1, a2, a3);
        if (lane == 0) atomicAdd(&eb.psum[p], S);
    }
}

// ---------------- out = x + agg / S for both node types; optional bf16 emit ----------------
struct AxpyBatch {
    const float* xin[2];
    const float* agg[2];
    const float* gsum[2];
    float* out[2];
    __nv_bfloat16* outb[2];
    int n4[2];
};

__global__ void axpy_batch(AxpyBatch ab)
{
    const int t = blockIdx.y;
    int i = blockIdx.x * blockDim.x + threadIdx.x;
    if (i >= ab.n4[t]) return;
    float inv = 1.0f / *ab.gsum[t];
    float4 x = ((const float4*)ab.xin[t])[i];
    float4 a = ((const float4*)ab.agg[t])[i];
    float4 o;
    o.x = fmaf(inv, a.x, x.x);
    o.y = fmaf(inv, a.y, x.y);
    o.z = fmaf(inv, a.z, x.z);
    o.w = fmaf(inv, a.w, x.w);
    ((float4*)ab.out[t])[i] = o;
    if (ab.outb[t]) {
        __nv_bfloat162 lo = __floats2bfloat162_rn(o.x, o.y);
        __nv_bfloat162 hi = __floats2bfloat162_rn(o.z, o.w);
        uint2 ob;
        ob.x = *(unsigned int*)&lo;
        ob.y = *(unsigned int*)&hi;
        ((uint2*)ab.outb[t])[i] = ob;
    }
}

// ---------------- host-side orchestration ----------------
#define GEMM_SMEM (2 * 128 * GSTRIDE * (int)sizeof(__nv_bfloat16))

extern "C" void kernel_launch(void* const* d_in, const int* in_sizes, int n_in,
                              void* d_out, int out_size)
{
    const float* x_user = (const float*)d_in[0];
    const float* x_item = (const float*)d_in[1];
    const int*   ei_ui  = (const int*)d_in[2];
    const int*   ei_iu  = (const int*)d_in[3];
    const float* q_w_user = (const float*)d_in[4];
    const float* q_b_user = (const float*)d_in[5];
    const float* k_w_user = (const float*)d_in[6];
    const float* k_b_user = (const float*)d_in[7];
    const float* v_w_user = (const float*)d_in[8];
    const float* v_b_user = (const float*)d_in[9];
    const float* q_w_item = (const float*)d_in[10];
    const float* q_b_item = (const float*)d_in[11];
    const float* k_w_item = (const float*)d_in[12];
    const float* k_b_item = (const float*)d_in[13];
    const float* v_w_item = (const float*)d_in[14];
    const float* v_b_item = (const float*)d_in[15];
    const float* W_ui = (const float*)d_in[16];
    const float* W_iu = (const float*)d_in[17];

    const int NU = in_sizes[0] / D;
    const int NI = in_sizes[1] / D;
    const int E_ui = in_sizes[2] / 2;
    const int E_iu = in_sizes[3] / 2;

    cudaFuncSetAttribute(gemm_batch, cudaFuncAttributeMaxDynamicSharedMemorySize, GEMM_SMEM);

    float *yu, *yi, *agg0, *agg1, *cb, *psum;
    __nv_bfloat16 *xbu, *xbi, *qb0, *qb1, *kb0, *kb1, *vb0, *vb1, *Mtb, *Kb, *Vb;
    int *off_ui, *off_iu, *src_ui_c, *src_iu_c, *tmp;
    cudaGetSymbolAddress((void**)&yu, g_yu);
    cudaGetSymbolAddress((void**)&yi, g_yi);
    cudaGetSymbolAddress((void**)&agg0, g_agg);      // [2][MAXN*D]
    agg1 = agg0 + (size_t)MAXN * D;
    cudaGetSymbolAddress((void**)&xbu, g_xbu);
    cudaGetSymbolAddress((void**)&xbi, g_xbi);
    cudaGetSymbolAddress((void**)&qb0, g_q);
    qb1 = qb0 + (size_t)MAXN * D;
    cudaGetSymbolAddress((void**)&kb0, g_k);
    kb1 = kb0 + (size_t)MAXN * D;
    cudaGetSymbolAddress((void**)&vb0, g_v);
    vb1 = vb0 + (size_t)MAXN * D;
    cudaGetSymbolAddress((void**)&Mtb, g_Mtb);       // [2][D*D]
    cudaGetSymbolAddress((void**)&Kb, g_Kb);
    cudaGetSymbolAddress((void**)&Vb, g_Vb);
    cudaGetSymbolAddress((void**)&cb, g_cb);         // [2][D]
    cudaGetSymbolAddress((void**)&psum, g_sum);
    cudaGetSymbolAddress((void**)&off_ui, g_off_ui);
    cudaGetSymbolAddress((void**)&off_iu, g_off_iu);
    cudaGetSymbolAddress((void**)&src_ui_c, g_src_ui);
    cudaGetSymbolAddress((void**)&src_iu_c, g_src_iu);
    cudaGetSymbolAddress((void**)&tmp, g_tmp);

    const int* src_ui = ei_ui;
    const int* dst_ui = ei_ui + E_ui;
    const int* src_iu = ei_iu;
    const int* dst_iu = ei_iu + E_iu;

    // --- CSR by dst for each edge type (stores src directly; built once, used by both layers) ---
    cudaMemsetAsync(tmp, 0, (size_t)NI * sizeof(int));
    count_kernel<<<1024, 256>>>(dst_ui, tmp, E_ui);
    scan_excl_kernel<<<1, 1024>>>(tmp, off_ui, NI);
    cudaMemcpyAsync(tmp, off_ui, (size_t)NI * sizeof(int), cudaMemcpyDeviceToDevice);
    fill_kernel<<<1024, 256>>>(dst_ui, src_ui, tmp, src_ui_c, E_ui);

    cudaMemsetAsync(tmp, 0, (size_t)NU * sizeof(int));
    count_kernel<<<1024, 256>>>(dst_iu, tmp, E_iu);
    scan_excl_kernel<<<1, 1024>>>(tmp, off_iu, NU);
    cudaMemcpyAsync(tmp, off_iu, (size_t)NU * sizeof(int), cudaMemcpyDeviceToDevice);
    fill_kernel<<<1024, 256>>>(dst_iu, src_iu, tmp, src_iu_c, E_iu);

    // --- bf16 copies of layer-0 inputs ---
    conv_b16<<<(NU * D / 4 + 255) / 256, 256>>>(x_user, xbu, NU * D / 4);
    conv_b16<<<(NI * D / 4 + 255) / 256, 256>>>(x_item, xbi, NI * D / 4);

    float* out_f = (float*)d_out;
    const int maxN = (NU > NI) ? NU : NI;

    for (int l = 0; l < 2; ++l) {
        const float* in_u = (l == 0) ? x_user : yu;
        const float* in_i = (l == 0) ? x_item : yi;
        float* out_u = (l == 0) ? yu : out_f;
        float* out_i = (l == 0) ? yi : (out_f + (size_t)NU * D);

        const size_t wo = (size_t)l * D * D;
        const size_t bo = (size_t)l * D;

        // pass 0: user->item (q/v from user, k from item, W_ui, agg into items)
        // pass 1: item->user (q/v from item, k from user, W_iu, agg into users)
        PrepBatch pb;
        pb.qw[0] = q_w_user + wo; pb.qb[0] = q_b_user + bo; pb.W[0] = W_ui + wo;
        pb.kw[0] = k_w_item + wo; pb.vw[0] = v_w_user + wo;
        pb.qw[1] = q_w_item + wo; pb.qb[1] = q_b_item + bo; pb.W[1] = W_iu + wo;
        pb.kw[1] = k_w_user + wo; pb.vw[1] = v_w_item + wo;
        pb.Mtb[0] = Mtb;           pb.Mtb[1] = Mtb + D * D;
        pb.cb[0]  = cb;            pb.cb[1]  = cb + D;
        pb.Kb[0]  = Kb;            pb.Kb[1]  = Kb + D * D;
        pb.Vb[0]  = Vb;            pb.Vb[1]  = Vb + D * D;
        pb.psum   = psum;
        prep_batch<<<dim3(193, 2), 256>>>(pb);

        GemmBatch gb;
        // pass 0
        gb.X[0] = xbu; gb.W[0] = Mtb;          gb.bias[0] = cb;            gb.C[0] = qb0; gb.N[0] = NU;
        gb.X[1] = xbi; gb.W[1] = Kb;           gb.bias[1] = k_b_item + bo; gb.C[1] = kb0; gb.N[1] = NI;
        gb.X[2] = xbu; gb.W[2] = Vb;           gb.bias[2] = v_b_user + bo; gb.C[2] = vb0; gb.N[2] = NU;
        // pass 1
        gb.X[3] = xbi; gb.W[3] = Mtb + D * D;  gb.bias[3] = cb + D;        gb.C[3] = qb1; gb.N[3] = NI;
        gb.X[4] = xbu; gb.W[4] = Kb + D * D;   gb.bias[4] = k_b_user + bo; gb.C[4] = kb1; gb.N[4] = NU;
        gb.X[5] = xbi; gb.W[5] = Vb + D * D;   gb.bias[5] = v_b_item + bo; gb.C[5] = vb1; gb.N[5] = NI;
        gemm_batch<<<dim3((maxN + 127) / 128, 6), 256, GEMM_SMEM>>>(gb);

        EdgeBatch eb;
        eb.q[0] = qb0; eb.k[0] = kb0; eb.v[0] = vb0;
        eb.off[0] = off_ui; eb.csrc[0] = src_ui_c; eb.agg[0] = agg0; eb.n[0] = NI;
        eb.q[1] = qb1; eb.k[1] = kb1; eb.v[1] = vb1;
        eb.off[1] = off_iu; eb.csrc[1] = src_iu_c; eb.agg[1] = agg1; eb.n[1] = NU;
        eb.psum = psum;
        fused_edge_batch<<<dim3(1024, 2), 256>>>(eb);

        AxpyBatch ab;
        ab.xin[0] = in_u; ab.agg[0] = agg1; ab.gsum[0] = psum + 1; ab.out[0] = out_u;
        ab.outb[0] = (l == 0) ? xbu : (__nv_bfloat16*)nullptr; ab.n4[0] = NU * D / 4;
        ab.xin[1] = in_i; ab.agg[1] = agg0; ab.gsum[1] = psum + 0; ab.out[1] = out_i;
        ab.outb[1] = (l == 0) ? xbi : (__nv_bfloat16*)nullptr; ab.n4[1] = NI * D / 4;
        axpy_batch<<<dim3((maxN * D / 4 + 255) / 256, 2), 256>>>(ab);
    }
}